// round 4
// baseline (speedup 1.0000x reference)
#include <cuda_runtime.h>
#include <cstdint>

#define Bn   4
#define Ln   8
#define Nn   2048
#define Cn   32
#define MIDn 64
#define OUTn 128
#define Mn   1024
#define KSn  32
#define KMn  192
#define BLn  32
#define FLTMAXC 3.4028234663852886e38f

__device__ float g_ft[BLn * Nn * Cn];
__device__ float g_x[Bn * Ln * KMn * Mn];
__device__ float g_W2[MIDn * 96];
__device__ float g_mean[Ln * KMn];
__device__ float g_rstd[Ln * KMn];

// ---------------------------------------------------------------------------
// 0) no-op kernels: shift ncu's "-s 5 -c 1" capture window onto fps_kernel
// ---------------------------------------------------------------------------
__global__ void nop_kernel() {}

// ---------------------------------------------------------------------------
// 1) Transpose features (B,L,C,N) -> g_ft[frame][n][c]; block(0,0) also builds W2
// ---------------------------------------------------------------------------
__global__ void transpose_feat_kernel(const float* __restrict__ feat,
                                      const float* __restrict__ cdw,
                                      const float* __restrict__ cfw) {
    __shared__ float sm[32][33];
    int f  = blockIdx.y;
    int n0 = blockIdx.x * 32;
    int tx = threadIdx.x, ty = threadIdx.y;
    sm[ty][tx] = feat[((size_t)f * Cn + ty) * Nn + n0 + tx];
    if (blockIdx.x == 0 && blockIdx.y == 0) {
        int tid = ty * 32 + tx;
        for (int idx = tid; idx < MIDn * 96; idx += 1024) {
            int oo = idx / 96, r = idx % 96, c = r / 3, d = r % 3;
            g_W2[idx] = cfw[oo * Cn + c] * cdw[oo * 3 + d];
        }
    }
    __syncthreads();
    g_ft[((size_t)f * Nn + n0 + ty) * Cn + tx] = sm[tx][ty];
}

// ---------------------------------------------------------------------------
// 2) FPS: 32 blocks x 256 threads, 8 points/thread in registers.
//    Per-thread argmax is a SEL tree (no serial predicate-guard chain).
//    Warp: redux max val + redux min idx. Block: 8 leaders write packed u64
//    (valbits<<32 | ~idx) to parity double-buffered smem; ONE barrier; every
//    thread redundantly max-reduces the 8 words.
// ---------------------------------------------------------------------------
__global__ void __launch_bounds__(256)
fps_kernel(const float* __restrict__ xyz, float* __restrict__ dout) {
    __shared__ float4 pts[Nn];                  // 32 KB
    __shared__ float  anch[Mn * 3];             // 12 KB
    __shared__ unsigned long long pk[2][8];

    int f = blockIdx.x;
    int tid = threadIdx.x, lane = tid & 31;
    int wid = tid >> 5;

    const float* base = xyz + (size_t)f * Nn * 3;
    for (int p = tid; p < Nn; p += 256)
        pts[p] = make_float4(base[3*p], base[3*p+1], base[3*p+2], 0.f);
    __syncthreads();

    float px[8], py[8], pz[8], md[8];
#pragma unroll
    for (int j = 0; j < 8; ++j) {
        float4 q = pts[tid + j * 256];
        px[j] = q.x; py[j] = q.y; pz[j] = q.z;
        md[j] = FLTMAXC;
    }
    float sx = pts[0].x, sy = pts[0].y, sz = pts[0].z;

    for (int i = 0; i < Mn; ++i) {
        if (tid == 0) { anch[3*i] = sx; anch[3*i+1] = sy; anch[3*i+2] = sz; }

        float nv[8];
#pragma unroll
        for (int j = 0; j < 8; ++j) {
            float dx = px[j] - sx, dy = py[j] - sy, dz = pz[j] - sz;
            float d  = fmaf(dx, dx, fmaf(dy, dy, dz * dz));
            float nm = fminf(md[j], d);
            md[j] = nm;
            nv[j] = nm;
        }
        // tournament argmax, >= prefers the lower-index (left) side => exact
        // "max value, lowest index" tie-break semantics.
        float v0 = (nv[0] >= nv[1]) ? nv[0] : nv[1];
        int   i0 = (nv[0] >= nv[1]) ? 0 : 1;
        float v1 = (nv[2] >= nv[3]) ? nv[2] : nv[3];
        int   i1 = (nv[2] >= nv[3]) ? 2 : 3;
        float v2 = (nv[4] >= nv[5]) ? nv[4] : nv[5];
        int   i2 = (nv[4] >= nv[5]) ? 4 : 5;
        float v3 = (nv[6] >= nv[7]) ? nv[6] : nv[7];
        int   i3 = (nv[6] >= nv[7]) ? 6 : 7;
        float va = (v0 >= v1) ? v0 : v1;
        int   ia = (v0 >= v1) ? i0 : i1;
        float vb = (v2 >= v3) ? v2 : v3;
        int   ib = (v2 >= v3) ? i2 : i3;
        float bvv = (va >= vb) ? va : vb;
        int   bj  = (va >= vb) ? ia : ib;
        unsigned bi = (unsigned)(tid + bj * 256);

        // distances >= 0: float bits order-preserving as u32
        unsigned vbits = __float_as_uint(bvv);
        unsigned wmax  = __reduce_max_sync(0xffffffffu, vbits);
        unsigned cidx  = (vbits == wmax) ? bi : 0xffffffffu;
        unsigned widx  = __reduce_min_sync(0xffffffffu, cidx);

        int s = i & 1;
        if (lane == 0)
            pk[s][wid] = ((unsigned long long)wmax << 32) |
                         (unsigned long long)(~widx);
        __syncthreads();

        unsigned long long m0 = pk[s][0], m1 = pk[s][1];
        unsigned long long m2 = pk[s][2], m3 = pk[s][3];
        unsigned long long m4 = pk[s][4], m5 = pk[s][5];
        unsigned long long m6 = pk[s][6], m7 = pk[s][7];
        unsigned long long a0 = (m0 > m1) ? m0 : m1;
        unsigned long long a1 = (m2 > m3) ? m2 : m3;
        unsigned long long a2 = (m4 > m5) ? m4 : m5;
        unsigned long long a3 = (m6 > m7) ? m6 : m7;
        unsigned long long b0 = (a0 > a1) ? a0 : a1;
        unsigned long long b1 = (a2 > a3) ? a2 : a3;
        unsigned long long mm = (b0 > b1) ? b0 : b1;
        int idx = (int)(~(unsigned)mm);
        float4 spv = pts[idx];
        sx = spv.x; sy = spv.y; sz = spv.z;
    }
    __syncthreads();
    float* o = dout + (size_t)f * Mn * 3;
    const float4* a4 = (const float4*)anch;
    for (int p = tid; p < (Mn * 3) / 4; p += 256)
        ((float4*)o)[p] = a4[p];
}

// ---------------------------------------------------------------------------
// 3) Ball query + grouped conv via moment S, fused small GEMM.
// ---------------------------------------------------------------------------
__global__ void __launch_bounds__(512)
group_conv_kernel(const float* __restrict__ xyz,
                  const float* __restrict__ anchors)
{
    extern __shared__ char smraw[];
    float4* npts = (float4*)smraw;                        // 32768 B
    float*  Ssm  = (float*)(smraw + 32768);               // 24576
    float*  W2   = (float*)(smraw + 32768 + 24576);       // 24576
    int*    cand = (int*)  (smraw + 32768 + 49152);       // 2048

    int tile = blockIdx.x;
    int o    = blockIdx.y;
    int f    = blockIdx.z;
    int b = f >> 3, l = f & 7;
    int tid = threadIdx.x, lane = tid & 31, wid = tid >> 5;

    int ln = l + o - 1;
    if (ln < 0 || ln >= Ln) {
        for (int idx = tid; idx < 4096; idx += 512) {
            int kk = idx >> 6, mm = idx & 63;
            g_x[((size_t)f * KMn + o * MIDn + kk) * Mn + tile * 64 + mm] = 0.f;
        }
        return;
    }
    int nbr = b * Ln + ln;

    const float* nb = xyz + (size_t)nbr * Nn * 3;
    for (int p = tid; p < Nn; p += 512)
        npts[p] = make_float4(nb[3*p], nb[3*p+1], nb[3*p+2], 0.f);
    for (int idx = tid; idx < MIDn * 96; idx += 512)
        W2[idx] = g_W2[idx];
    __syncthreads();

    int* candw = cand + wid * 32;
    const float* fb = g_ft + (size_t)nbr * Nn * Cn;

    for (int aa = 0; aa < 4; ++aa) {
        int a_local = wid * 4 + aa;
        int a = tile * 64 + a_local;
        const float* ap = anchors + ((size_t)f * Mn + a) * 3;
        float ax = ap[0], ay = ap[1], az = ap[2];

        int cnt = 0;
        for (int basej = 0; basej < Nn && cnt < KSn; basej += 32) {
            int j = basej + lane;
            float4 p = npts[j];
            float dx = p.x - ax, dy = p.y - ay, dz = p.z - az;
            float d2 = fmaf(dx, dx, fmaf(dy, dy, dz * dz));
            bool in = d2 < 0.04f;
            unsigned msk = __ballot_sync(0xffffffffu, in);
            if (in) {
                int pos = cnt + __popc(msk & ((1u << lane) - 1u));
                if (pos < KSn) candw[pos] = j;
            }
            cnt += __popc(msk);
        }
        __syncwarp();
        int cc = cnt < KSn ? cnt : KSn;
        int fill0 = (cc > 0) ? candw[0] : 0;
        __syncwarp();
        if (lane >= cc) candw[lane] = fill0;
        __syncwarp();

        float a0 = 0.f, a1 = 0.f, a2 = 0.f;
#pragma unroll 8
        for (int k = 0; k < KSn; ++k) {
            int j = candw[k];
            float4 p = npts[j];
            float fv = fb[(size_t)j * Cn + lane];
            a0 = fmaf(fv, p.x - ax, a0);
            a1 = fmaf(fv, p.y - ay, a1);
            a2 = fmaf(fv, p.z - az, a2);
        }
        Ssm[a_local * 96 + lane * 3 + 0] = a0;
        Ssm[a_local * 96 + lane * 3 + 1] = a1;
        Ssm[a_local * 96 + lane * 3 + 2] = a2;
    }
    __syncthreads();

    int o0 = (tid & 15) * 4;
    int aq = (tid >> 4) * 2;
    float acc[4][2] = {};
    for (int i = 0; i < 96; i += 4) {
        float4 w[4], s[2];
#pragma unroll
        for (int q = 0; q < 4; ++q) w[q] = *(const float4*)&W2[(o0 + q) * 96 + i];
#pragma unroll
        for (int r = 0; r < 2; ++r) s[r] = *(const float4*)&Ssm[(aq + r) * 96 + i];
#pragma unroll
        for (int q = 0; q < 4; ++q)
#pragma unroll
            for (int r = 0; r < 2; ++r)
                acc[q][r] += w[q].x * s[r].x + w[q].y * s[r].y
                           + w[q].z * s[r].z + w[q].w * s[r].w;
    }
#pragma unroll
    for (int q = 0; q < 4; ++q)
#pragma unroll
        for (int r = 0; r < 2; ++r)
            g_x[((size_t)f * KMn + o * MIDn + o0 + q) * Mn + tile * 64 + aq + r] = acc[q][r];
}

// ---------------------------------------------------------------------------
// 4) BN stats per (l, km) over 4096 values, float4 vectorized
// ---------------------------------------------------------------------------
__global__ void stats_kernel() {
    int pair = blockIdx.x;
    int l = pair / KMn, km = pair % KMn;
    int tid = threadIdx.x;
    float s1 = 0.f, s2 = 0.f;
#pragma unroll
    for (int b = 0; b < Bn; ++b) {
        const float4* row = (const float4*)(g_x + ((size_t)((b * Ln + l) * KMn + km)) * Mn);
#pragma unroll
        for (int m = 0; m < 2; ++m) {
            float4 v = row[tid + m * 128];
            s1 += v.x + v.y + v.z + v.w;
            s2 += v.x*v.x + v.y*v.y + v.z*v.z + v.w*v.w;
        }
    }
    __shared__ float sh1[4], sh2[4];
#pragma unroll
    for (int off = 16; off > 0; off >>= 1) {
        s1 += __shfl_down_sync(0xffffffffu, s1, off);
        s2 += __shfl_down_sync(0xffffffffu, s2, off);
    }
    int lane = tid & 31, w = tid >> 5;
    if (lane == 0) { sh1[w] = s1; sh2[w] = s2; }
    __syncthreads();
    if (tid == 0) {
        float t1 = sh1[0] + sh1[1] + sh1[2] + sh1[3];
        float t2 = sh2[0] + sh2[1] + sh2[2] + sh2[3];
        float mean = t1 * (1.f / 4096.f);
        float var  = t2 * (1.f / 4096.f) - mean * mean;
        g_mean[pair] = mean;
        g_rstd[pair] = rsqrtf(var + 1e-5f);
    }
}

// ---------------------------------------------------------------------------
// 5) Fused BN + ReLU + temporal GEMM
// ---------------------------------------------------------------------------
__global__ void __launch_bounds__(256)
bn_gemm_kernel(const float* __restrict__ gamma, const float* __restrict__ beta,
               const float* __restrict__ tw, float* __restrict__ dout)
{
    extern __shared__ float smf[];
    float* xsm  = smf;           // [192][128]
    float* twsm = smf + 24576;   // [128][192]

    int f = blockIdx.y, l = f & 7;
    int mb = blockIdx.x * 128;
    int tid = threadIdx.x;

    for (int idx = tid; idx < KMn * 128; idx += 256) {
        int k = idx >> 7, m = idx & 127;
        float v  = g_x[((size_t)f * KMn + k) * Mn + mb + m];
        float xn = (v - g_mean[l * KMn + k]) * g_rstd[l * KMn + k] * gamma[k] + beta[k];
        xsm[idx] = fmaxf(xn, 0.f);
    }
    for (int idx = tid; idx < OUTn * KMn; idx += 256) twsm[idx] = tw[idx];
    __syncthreads();

    int o0 = (tid >> 4) * 8;
    int m0 = (tid & 15) * 8;
    float acc[8][8] = {};
    for (int k = 0; k < KMn; k += 4) {
        float4 wv[8];
#pragma unroll
        for (int q = 0; q < 8; ++q) wv[q] = *(const float4*)&twsm[(o0 + q) * KMn + k];
        float4 xa[4], xb[4];
#pragma unroll
        for (int j = 0; j < 4; ++j) {
            xa[j] = *(const float4*)&xsm[(k + j) * 128 + m0];
            xb[j] = *(const float4*)&xsm[(k + j) * 128 + m0 + 4];
        }
#pragma unroll
        for (int q = 0; q < 8; ++q) {
            const float* wq = (const float*)&wv[q];
#pragma unroll
            for (int j = 0; j < 4; ++j) {
                float w = wq[j];
                const float* pa = (const float*)&xa[j];
                const float* pb = (const float*)&xb[j];
#pragma unroll
                for (int r = 0; r < 4; ++r) {
                    acc[q][r]     += w * pa[r];
                    acc[q][4 + r] += w * pb[r];
                }
            }
        }
    }
    float* outb = dout + (size_t)BLn * Mn * 3 + ((size_t)f * OUTn) * Mn + mb;
#pragma unroll
    for (int q = 0; q < 8; ++q)
#pragma unroll
        for (int r = 0; r < 8; ++r)
            outb[(size_t)(o0 + q) * Mn + m0 + r] = acc[q][r];
}

// ---------------------------------------------------------------------------
extern "C" void kernel_launch(void* const* d_in, const int* in_sizes, int n_in,
                              void* d_out, int out_size) {
    const float* xyzs     = (const float*)d_in[0];
    const float* features = (const float*)d_in[1];
    const float* cdw      = (const float*)d_in[2];
    const float* cfw      = (const float*)d_in[3];
    const float* gamma    = (const float*)d_in[4];
    const float* beta     = (const float*)d_in[5];
    const float* tw       = (const float*)d_in[6];
    float* out = (float*)d_out;

    cudaFuncSetAttribute(group_conv_kernel, cudaFuncAttributeMaxDynamicSharedMemorySize, 84000);
    cudaFuncSetAttribute(bn_gemm_kernel,    cudaFuncAttributeMaxDynamicSharedMemorySize, 196608);

    transpose_feat_kernel<<<dim3(64, 32), dim3(32, 32)>>>(features, cdw, cfw);
    nop_kernel<<<1, 32>>>();   // shift ncu capture window
    nop_kernel<<<1, 32>>>();   // (targets fps_kernel at skip-5)
    fps_kernel<<<32, 256>>>(xyzs, out);
    group_conv_kernel<<<dim3(16, 3, 32), 512, 84000>>>(xyzs, out);
    stats_kernel<<<Ln * KMn, 128>>>();
    bn_gemm_kernel<<<dim3(8, 32), 256, 196608>>>(gamma, beta, tw, out);
}

// round 5
// speedup vs baseline: 1.0554x; 1.0554x over previous
#include <cuda_runtime.h>
#include <cstdint>

#define Bn   4
#define Ln   8
#define Nn   2048
#define Cn   32
#define MIDn 64
#define OUTn 128
#define Mn   1024
#define KSn  32
#define KMn  192
#define BLn  32
#define FLTMAXC 3.4028234663852886e38f

// Packed f32x2 helpers (sm_103a native; per-lane IEEE identical to scalar)
#define MUL2(out, a, b) asm("mul.rn.f32x2 %0, %1, %2;" : "=l"(out) : "l"(a), "l"(b))
#define ADD2(out, a, b) asm("add.rn.f32x2 %0, %1, %2;" : "=l"(out) : "l"(a), "l"(b))
#define FMA2(out, a, b, c) asm("fma.rn.f32x2 %0, %1, %2, %3;" : "=l"(out) : "l"(a), "l"(b), "l"(c))
#define PACK2(out, lo, hi) asm("mov.b64 %0, {%1, %2};" : "=l"(out) : "r"(lo), "r"(hi))
#define UNPACK2(lo, hi, in) asm("mov.b64 {%0, %1}, %2;" : "=r"(lo), "=r"(hi) : "l"(in))

__device__ float g_ft[BLn * Nn * Cn];
__device__ float g_x[Bn * Ln * KMn * Mn];
__device__ float g_W2[MIDn * 96];
__device__ float g_mean[Ln * KMn];
__device__ float g_rstd[Ln * KMn];

__global__ void nop_kernel() {}

// ---------------------------------------------------------------------------
// 1) Transpose features (B,L,C,N) -> g_ft[frame][n][c]; block(0,0) builds W2
// ---------------------------------------------------------------------------
__global__ void transpose_feat_kernel(const float* __restrict__ feat,
                                      const float* __restrict__ cdw,
                                      const float* __restrict__ cfw) {
    __shared__ float sm[32][33];
    int f  = blockIdx.y;
    int n0 = blockIdx.x * 32;
    int tx = threadIdx.x, ty = threadIdx.y;
    sm[ty][tx] = feat[((size_t)f * Cn + ty) * Nn + n0 + tx];
    if (blockIdx.x == 0 && blockIdx.y == 0) {
        int tid = ty * 32 + tx;
        for (int idx = tid; idx < MIDn * 96; idx += 1024) {
            int oo = idx / 96, r = idx % 96, c = r / 3, d = r % 3;
            g_W2[idx] = cfw[oo * Cn + c] * cdw[oo * 3 + d];
        }
    }
    __syncthreads();
    g_ft[((size_t)f * Nn + n0 + ty) * Cn + tx] = sm[tx][ty];
}

// ---------------------------------------------------------------------------
// 2) FPS: 32 blocks x 256 threads, 8 points/thread, f32x2-packed distances.
//    Per-thread SEL-tree argmax, warp redux, block reduce via packed u64 in
//    parity double-buffered smem with ONE barrier per iteration.
// ---------------------------------------------------------------------------
__global__ void __launch_bounds__(256)
fps_kernel(const float* __restrict__ xyz, float* __restrict__ dout) {
    __shared__ float4 pts[Nn];                  // 32 KB
    __shared__ float  anch[Mn * 3];             // 12 KB
    __shared__ unsigned long long pk[2][8];

    int f = blockIdx.x;
    int tid = threadIdx.x, lane = tid & 31;
    int wid = tid >> 5;

    const float* base = xyz + (size_t)f * Nn * 3;
    for (int p = tid; p < Nn; p += 256)
        pts[p] = make_float4(base[3*p], base[3*p+1], base[3*p+2], 0.f);
    __syncthreads();

    // pack pairs (2q, 2q+1): point index = tid + j*256
    unsigned long long px2[4], py2[4], pz2[4];
    float md[8];
#pragma unroll
    for (int q = 0; q < 4; ++q) {
        float4 a = pts[tid + (2*q) * 256];
        float4 b = pts[tid + (2*q+1) * 256];
        PACK2(px2[q], __float_as_uint(a.x), __float_as_uint(b.x));
        PACK2(py2[q], __float_as_uint(a.y), __float_as_uint(b.y));
        PACK2(pz2[q], __float_as_uint(a.z), __float_as_uint(b.z));
        md[2*q] = FLTMAXC; md[2*q+1] = FLTMAXC;
    }
    float sx = pts[0].x, sy = pts[0].y, sz = pts[0].z;

    for (int i = 0; i < Mn; ++i) {
        if (tid == 0) { anch[3*i] = sx; anch[3*i+1] = sy; anch[3*i+2] = sz; }

        unsigned long long nsx2, nsy2, nsz2;
        unsigned nx = __float_as_uint(-sx), ny = __float_as_uint(-sy), nz = __float_as_uint(-sz);
        PACK2(nsx2, nx, nx); PACK2(nsy2, ny, ny); PACK2(nsz2, nz, nz);

        float nv[8];
#pragma unroll
        for (int q = 0; q < 4; ++q) {
            unsigned long long dx, dy, dz, zz, d2;
            ADD2(dx, px2[q], nsx2);             // px - sx (exact: a + (-b))
            ADD2(dy, py2[q], nsy2);
            ADD2(dz, pz2[q], nsz2);
            MUL2(zz, dz, dz);
            FMA2(d2, dy, dy, zz);
            FMA2(d2, dx, dx, d2);
            unsigned ulo, uhi;
            UNPACK2(ulo, uhi, d2);
            float nmlo = fminf(md[2*q],   __uint_as_float(ulo));
            float nmhi = fminf(md[2*q+1], __uint_as_float(uhi));
            md[2*q] = nmlo; md[2*q+1] = nmhi;
            nv[2*q] = nmlo; nv[2*q+1] = nmhi;
        }
        // tournament argmax, >= prefers lower-index side (exact tie-break)
        float v0 = (nv[0] >= nv[1]) ? nv[0] : nv[1];
        int   i0 = (nv[0] >= nv[1]) ? 0 : 1;
        float v1 = (nv[2] >= nv[3]) ? nv[2] : nv[3];
        int   i1 = (nv[2] >= nv[3]) ? 2 : 3;
        float v2 = (nv[4] >= nv[5]) ? nv[4] : nv[5];
        int   i2 = (nv[4] >= nv[5]) ? 4 : 5;
        float v3 = (nv[6] >= nv[7]) ? nv[6] : nv[7];
        int   i3 = (nv[6] >= nv[7]) ? 6 : 7;
        float va = (v0 >= v1) ? v0 : v1;
        int   ia = (v0 >= v1) ? i0 : i1;
        float vb = (v2 >= v3) ? v2 : v3;
        int   ib = (v2 >= v3) ? i2 : i3;
        float bvv = (va >= vb) ? va : vb;
        int   bj  = (va >= vb) ? ia : ib;
        unsigned bi = (unsigned)(tid + bj * 256);

        unsigned vbits = __float_as_uint(bvv);       // distances >= 0
        unsigned wmax  = __reduce_max_sync(0xffffffffu, vbits);
        unsigned cidx  = (vbits == wmax) ? bi : 0xffffffffu;
        unsigned widx  = __reduce_min_sync(0xffffffffu, cidx);

        int s = i & 1;
        if (lane == 0)
            pk[s][wid] = ((unsigned long long)wmax << 32) |
                         (unsigned long long)(~widx);
        __syncthreads();

        unsigned long long m0 = pk[s][0], m1 = pk[s][1];
        unsigned long long m2 = pk[s][2], m3 = pk[s][3];
        unsigned long long m4 = pk[s][4], m5 = pk[s][5];
        unsigned long long m6 = pk[s][6], m7 = pk[s][7];
        unsigned long long a0 = (m0 > m1) ? m0 : m1;
        unsigned long long a1 = (m2 > m3) ? m2 : m3;
        unsigned long long a2 = (m4 > m5) ? m4 : m5;
        unsigned long long a3 = (m6 > m7) ? m6 : m7;
        unsigned long long b0 = (a0 > a1) ? a0 : a1;
        unsigned long long b1 = (a2 > a3) ? a2 : a3;
        unsigned long long mm = (b0 > b1) ? b0 : b1;
        int idx = (int)(~(unsigned)mm);
        float4 spv = pts[idx];
        sx = spv.x; sy = spv.y; sz = spv.z;
    }
    __syncthreads();
    float* o = dout + (size_t)f * Mn * 3;
    const float4* a4 = (const float4*)anch;
    for (int p = tid; p < (Mn * 3) / 4; p += 256)
        ((float4*)o)[p] = a4[p];
}

// ---------------------------------------------------------------------------
// 3) Ball query + grouped conv via moment S. W2 read from global (L1/L2 hot).
//    smem = 58KB -> 3 blocks/SM.
// ---------------------------------------------------------------------------
__global__ void __launch_bounds__(512)
group_conv_kernel(const float* __restrict__ xyz,
                  const float* __restrict__ anchors)
{
    extern __shared__ char smraw[];
    float4* npts = (float4*)smraw;                        // 32768 B
    float*  Ssm  = (float*)(smraw + 32768);               // 24576
    int*    cand = (int*)  (smraw + 32768 + 24576);       // 2048

    int tile = blockIdx.x;
    int o    = blockIdx.y;
    int f    = blockIdx.z;
    int b = f >> 3, l = f & 7;
    int tid = threadIdx.x, lane = tid & 31, wid = tid >> 5;

    int ln = l + o - 1;
    if (ln < 0 || ln >= Ln) {
        for (int idx = tid; idx < 4096; idx += 512) {
            int kk = idx >> 6, mm = idx & 63;
            g_x[((size_t)f * KMn + o * MIDn + kk) * Mn + tile * 64 + mm] = 0.f;
        }
        return;
    }
    int nbr = b * Ln + ln;

    const float* nb = xyz + (size_t)nbr * Nn * 3;
    for (int p = tid; p < Nn; p += 512)
        npts[p] = make_float4(nb[3*p], nb[3*p+1], nb[3*p+2], 0.f);
    __syncthreads();

    int* candw = cand + wid * 32;
    const float* fb = g_ft + (size_t)nbr * Nn * Cn;

    for (int aa = 0; aa < 4; ++aa) {
        int a_local = wid * 4 + aa;
        int a = tile * 64 + a_local;
        const float* ap = anchors + ((size_t)f * Mn + a) * 3;
        float ax = ap[0], ay = ap[1], az = ap[2];

        int cnt = 0;
        for (int basej = 0; basej < Nn && cnt < KSn; basej += 32) {
            int j = basej + lane;
            float4 p = npts[j];
            float dx = p.x - ax, dy = p.y - ay, dz = p.z - az;
            float d2 = fmaf(dx, dx, fmaf(dy, dy, dz * dz));
            bool in = d2 < 0.04f;
            unsigned msk = __ballot_sync(0xffffffffu, in);
            if (in) {
                int pos = cnt + __popc(msk & ((1u << lane) - 1u));
                if (pos < KSn) candw[pos] = j;
            }
            cnt += __popc(msk);
        }
        __syncwarp();
        int cc = cnt < KSn ? cnt : KSn;
        int fill0 = (cc > 0) ? candw[0] : 0;
        __syncwarp();
        if (lane >= cc) candw[lane] = fill0;
        __syncwarp();

        float a0 = 0.f, a1 = 0.f, a2 = 0.f;
#pragma unroll 8
        for (int k = 0; k < KSn; ++k) {
            int j = candw[k];
            float4 p = npts[j];
            float fv = __ldg(&fb[(size_t)j * Cn + lane]);
            a0 = fmaf(fv, p.x - ax, a0);
            a1 = fmaf(fv, p.y - ay, a1);
            a2 = fmaf(fv, p.z - az, a2);
        }
        Ssm[a_local * 96 + lane * 3 + 0] = a0;
        Ssm[a_local * 96 + lane * 3 + 1] = a1;
        Ssm[a_local * 96 + lane * 3 + 2] = a2;
    }
    __syncthreads();

    // GEMM: W2 rows from global (heavily reused across 1536 blocks -> L1 hits)
    int o0 = (tid & 15) * 4;
    int aq = (tid >> 4) * 2;
    float acc[4][2] = {};
    for (int i = 0; i < 96; i += 4) {
        float4 w[4], s[2];
#pragma unroll
        for (int q = 0; q < 4; ++q) w[q] = __ldg((const float4*)&g_W2[(o0 + q) * 96 + i]);
#pragma unroll
        for (int r = 0; r < 2; ++r) s[r] = *(const float4*)&Ssm[(aq + r) * 96 + i];
#pragma unroll
        for (int q = 0; q < 4; ++q)
#pragma unroll
            for (int r = 0; r < 2; ++r)
                acc[q][r] += w[q].x * s[r].x + w[q].y * s[r].y
                           + w[q].z * s[r].z + w[q].w * s[r].w;
    }
#pragma unroll
    for (int q = 0; q < 4; ++q)
#pragma unroll
        for (int r = 0; r < 2; ++r)
            g_x[((size_t)f * KMn + o * MIDn + o0 + q) * Mn + tile * 64 + aq + r] = acc[q][r];
}

// ---------------------------------------------------------------------------
// 4) BN stats per (l, km) over 4096 values, float4 vectorized
// ---------------------------------------------------------------------------
__global__ void stats_kernel() {
    int pair = blockIdx.x;
    int l = pair / KMn, km = pair % KMn;
    int tid = threadIdx.x;
    float s1 = 0.f, s2 = 0.f;
#pragma unroll
    for (int b = 0; b < Bn; ++b) {
        const float4* row = (const float4*)(g_x + ((size_t)((b * Ln + l) * KMn + km)) * Mn);
#pragma unroll
        for (int m = 0; m < 2; ++m) {
            float4 v = row[tid + m * 128];
            s1 += v.x + v.y + v.z + v.w;
            s2 += v.x*v.x + v.y*v.y + v.z*v.z + v.w*v.w;
        }
    }
    __shared__ float sh1[4], sh2[4];
#pragma unroll
    for (int off = 16; off > 0; off >>= 1) {
        s1 += __shfl_down_sync(0xffffffffu, s1, off);
        s2 += __shfl_down_sync(0xffffffffu, s2, off);
    }
    int lane = tid & 31, w = tid >> 5;
    if (lane == 0) { sh1[w] = s1; sh2[w] = s2; }
    __syncthreads();
    if (tid == 0) {
        float t1 = sh1[0] + sh1[1] + sh1[2] + sh1[3];
        float t2 = sh2[0] + sh2[1] + sh2[2] + sh2[3];
        float mean = t1 * (1.f / 4096.f);
        float var  = t2 * (1.f / 4096.f) - mean * mean;
        g_mean[pair] = mean;
        g_rstd[pair] = rsqrtf(var + 1e-5f);
    }
}

// ---------------------------------------------------------------------------
// 5) Fused BN + ReLU + temporal GEMM
// ---------------------------------------------------------------------------
__global__ void __launch_bounds__(256)
bn_gemm_kernel(const float* __restrict__ gamma, const float* __restrict__ beta,
               const float* __restrict__ tw, float* __restrict__ dout)
{
    extern __shared__ float smf[];
    float* xsm  = smf;           // [192][128]
    float* twsm = smf + 24576;   // [128][192]

    int f = blockIdx.y, l = f & 7;
    int mb = blockIdx.x * 128;
    int tid = threadIdx.x;

    for (int idx = tid; idx < KMn * 128; idx += 256) {
        int k = idx >> 7, m = idx & 127;
        float v  = g_x[((size_t)f * KMn + k) * Mn + mb + m];
        float xn = (v - g_mean[l * KMn + k]) * g_rstd[l * KMn + k] * gamma[k] + beta[k];
        xsm[idx] = fmaxf(xn, 0.f);
    }
    for (int idx = tid; idx < OUTn * KMn; idx += 256) twsm[idx] = tw[idx];
    __syncthreads();

    int o0 = (tid >> 4) * 8;
    int m0 = (tid & 15) * 8;
    float acc[8][8] = {};
    for (int k = 0; k < KMn; k += 4) {
        float4 wv[8];
#pragma unroll
        for (int q = 0; q < 8; ++q) wv[q] = *(const float4*)&twsm[(o0 + q) * KMn + k];
        float4 xa[4], xb[4];
#pragma unroll
        for (int j = 0; j < 4; ++j) {
            xa[j] = *(const float4*)&xsm[(k + j) * 128 + m0];
            xb[j] = *(const float4*)&xsm[(k + j) * 128 + m0 + 4];
        }
#pragma unroll
        for (int q = 0; q < 8; ++q) {
            const float* wq = (const float*)&wv[q];
#pragma unroll
            for (int j = 0; j < 4; ++j) {
                float w = wq[j];
                const float* pa = (const float*)&xa[j];
                const float* pb = (const float*)&xb[j];
#pragma unroll
                for (int r = 0; r < 4; ++r) {
                    acc[q][r]     += w * pa[r];
                    acc[q][4 + r] += w * pb[r];
                }
            }
        }
    }
    float* outb = dout + (size_t)BLn * Mn * 3 + ((size_t)f * OUTn) * Mn + mb;
#pragma unroll
    for (int q = 0; q < 8; ++q)
#pragma unroll
        for (int r = 0; r < 8; ++r)
            outb[(size_t)(o0 + q) * Mn + m0 + r] = acc[q][r];
}

// ---------------------------------------------------------------------------
extern "C" void kernel_launch(void* const* d_in, const int* in_sizes, int n_in,
                              void* d_out, int out_size) {
    const float* xyzs     = (const float*)d_in[0];
    const float* features = (const float*)d_in[1];
    const float* cdw      = (const float*)d_in[2];
    const float* cfw      = (const float*)d_in[3];
    const float* gamma    = (const float*)d_in[4];
    const float* beta     = (const float*)d_in[5];
    const float* tw       = (const float*)d_in[6];
    float* out = (float*)d_out;

    cudaFuncSetAttribute(group_conv_kernel, cudaFuncAttributeMaxDynamicSharedMemorySize, 59392);
    cudaFuncSetAttribute(bn_gemm_kernel,    cudaFuncAttributeMaxDynamicSharedMemorySize, 196608);

    transpose_feat_kernel<<<dim3(64, 32), dim3(32, 32)>>>(features, cdw, cfw);
    nop_kernel<<<1, 32>>>();   // align ncu: group_conv becomes 4th launch
    fps_kernel<<<32, 256>>>(xyzs, out);
    group_conv_kernel<<<dim3(16, 3, 32), 512, 59392>>>(xyzs, out);
    stats_kernel<<<Ln * KMn, 128>>>();
    bn_gemm_kernel<<<dim3(8, 32), 256, 196608>>>(gamma, beta, tw, out);
}

// round 6
// speedup vs baseline: 1.1030x; 1.0450x over previous
#include <cuda_runtime.h>
#include <cstdint>

#define Bn   4
#define Ln   8
#define Nn   2048
#define Cn   32
#define MIDn 64
#define OUTn 128
#define Mn   1024
#define KSn  32
#define KMn  192
#define BLn  32
#define FLTMAXC 3.4028234663852886e38f

// Packed f32x2 helpers (sm_103a native; per-lane IEEE identical to scalar)
#define MUL2(out, a, b) asm("mul.rn.f32x2 %0, %1, %2;" : "=l"(out) : "l"(a), "l"(b))
#define ADD2(out, a, b) asm("add.rn.f32x2 %0, %1, %2;" : "=l"(out) : "l"(a), "l"(b))
#define FMA2(out, a, b, c) asm("fma.rn.f32x2 %0, %1, %2, %3;" : "=l"(out) : "l"(a), "l"(b), "l"(c))
#define PACK2(out, lo, hi) asm("mov.b64 %0, {%1, %2};" : "=l"(out) : "r"(lo), "r"(hi))
#define UNPACK2(lo, hi, in) asm("mov.b64 {%0, %1}, %2;" : "=r"(lo), "=r"(hi) : "l"(in))

__device__ float g_ft[BLn * Nn * Cn];
__device__ float g_x[Bn * Ln * KMn * Mn];
__device__ float g_W2[MIDn * 96];
__device__ float g_mean[Ln * KMn];
__device__ float g_rstd[Ln * KMn];

__global__ void nop_kernel() {}

// ---------------------------------------------------------------------------
// 1) Transpose features (B,L,C,N) -> g_ft[frame][n][c]; block(0,0) builds W2
// ---------------------------------------------------------------------------
__global__ void transpose_feat_kernel(const float* __restrict__ feat,
                                      const float* __restrict__ cdw,
                                      const float* __restrict__ cfw) {
    __shared__ float sm[32][33];
    int f  = blockIdx.y;
    int n0 = blockIdx.x * 32;
    int tx = threadIdx.x, ty = threadIdx.y;
    sm[ty][tx] = feat[((size_t)f * Cn + ty) * Nn + n0 + tx];
    if (blockIdx.x == 0 && blockIdx.y == 0) {
        int tid = ty * 32 + tx;
        for (int idx = tid; idx < MIDn * 96; idx += 1024) {
            int oo = idx / 96, r = idx % 96, c = r / 3, d = r % 3;
            g_W2[idx] = cfw[oo * Cn + c] * cdw[oo * 3 + d];
        }
    }
    __syncthreads();
    g_ft[((size_t)f * Nn + n0 + ty) * Cn + tx] = sm[tx][ty];
}

// ---------------------------------------------------------------------------
// 2) FPS: 32 blocks x 256 threads, 8 points/thread, f32x2-packed distances.
// ---------------------------------------------------------------------------
__global__ void __launch_bounds__(256)
fps_kernel(const float* __restrict__ xyz, float* __restrict__ dout) {
    __shared__ float4 pts[Nn];                  // 32 KB
    __shared__ float  anch[Mn * 3];             // 12 KB
    __shared__ unsigned long long pk[2][8];

    int f = blockIdx.x;
    int tid = threadIdx.x, lane = tid & 31;
    int wid = tid >> 5;

    const float* base = xyz + (size_t)f * Nn * 3;
    for (int p = tid; p < Nn; p += 256)
        pts[p] = make_float4(base[3*p], base[3*p+1], base[3*p+2], 0.f);
    __syncthreads();

    unsigned long long px2[4], py2[4], pz2[4];
    float md[8];
#pragma unroll
    for (int q = 0; q < 4; ++q) {
        float4 a = pts[tid + (2*q) * 256];
        float4 b = pts[tid + (2*q+1) * 256];
        PACK2(px2[q], __float_as_uint(a.x), __float_as_uint(b.x));
        PACK2(py2[q], __float_as_uint(a.y), __float_as_uint(b.y));
        PACK2(pz2[q], __float_as_uint(a.z), __float_as_uint(b.z));
        md[2*q] = FLTMAXC; md[2*q+1] = FLTMAXC;
    }
    float sx = pts[0].x, sy = pts[0].y, sz = pts[0].z;

    for (int i = 0; i < Mn; ++i) {
        if (tid == 0) { anch[3*i] = sx; anch[3*i+1] = sy; anch[3*i+2] = sz; }

        unsigned long long nsx2, nsy2, nsz2;
        unsigned nx = __float_as_uint(-sx), ny = __float_as_uint(-sy), nz = __float_as_uint(-sz);
        PACK2(nsx2, nx, nx); PACK2(nsy2, ny, ny); PACK2(nsz2, nz, nz);

        float nv[8];
#pragma unroll
        for (int q = 0; q < 4; ++q) {
            unsigned long long dx, dy, dz, zz, d2;
            ADD2(dx, px2[q], nsx2);
            ADD2(dy, py2[q], nsy2);
            ADD2(dz, pz2[q], nsz2);
            MUL2(zz, dz, dz);
            FMA2(d2, dy, dy, zz);
            FMA2(d2, dx, dx, d2);
            unsigned ulo, uhi;
            UNPACK2(ulo, uhi, d2);
            float nmlo = fminf(md[2*q],   __uint_as_float(ulo));
            float nmhi = fminf(md[2*q+1], __uint_as_float(uhi));
            md[2*q] = nmlo; md[2*q+1] = nmhi;
            nv[2*q] = nmlo; nv[2*q+1] = nmhi;
        }
        float v0 = (nv[0] >= nv[1]) ? nv[0] : nv[1];
        int   i0 = (nv[0] >= nv[1]) ? 0 : 1;
        float v1 = (nv[2] >= nv[3]) ? nv[2] : nv[3];
        int   i1 = (nv[2] >= nv[3]) ? 2 : 3;
        float v2 = (nv[4] >= nv[5]) ? nv[4] : nv[5];
        int   i2 = (nv[4] >= nv[5]) ? 4 : 5;
        float v3 = (nv[6] >= nv[7]) ? nv[6] : nv[7];
        int   i3 = (nv[6] >= nv[7]) ? 6 : 7;
        float va = (v0 >= v1) ? v0 : v1;
        int   ia = (v0 >= v1) ? i0 : i1;
        float vb = (v2 >= v3) ? v2 : v3;
        int   ib = (v2 >= v3) ? i2 : i3;
        float bvv = (va >= vb) ? va : vb;
        int   bj  = (va >= vb) ? ia : ib;
        unsigned bi = (unsigned)(tid + bj * 256);

        unsigned vbits = __float_as_uint(bvv);
        unsigned wmax  = __reduce_max_sync(0xffffffffu, vbits);
        unsigned cidx  = (vbits == wmax) ? bi : 0xffffffffu;
        unsigned widx  = __reduce_min_sync(0xffffffffu, cidx);

        int s = i & 1;
        if (lane == 0)
            pk[s][wid] = ((unsigned long long)wmax << 32) |
                         (unsigned long long)(~widx);
        __syncthreads();

        unsigned long long m0 = pk[s][0], m1 = pk[s][1];
        unsigned long long m2 = pk[s][2], m3 = pk[s][3];
        unsigned long long m4 = pk[s][4], m5 = pk[s][5];
        unsigned long long m6 = pk[s][6], m7 = pk[s][7];
        unsigned long long a0 = (m0 > m1) ? m0 : m1;
        unsigned long long a1 = (m2 > m3) ? m2 : m3;
        unsigned long long a2 = (m4 > m5) ? m4 : m5;
        unsigned long long a3 = (m6 > m7) ? m6 : m7;
        unsigned long long b0 = (a0 > a1) ? a0 : a1;
        unsigned long long b1 = (a2 > a3) ? a2 : a3;
        unsigned long long mm = (b0 > b1) ? b0 : b1;
        int idx = (int)(~(unsigned)mm);
        float4 spv = pts[idx];
        sx = spv.x; sy = spv.y; sz = spv.z;
    }
    __syncthreads();
    float* o = dout + (size_t)f * Mn * 3;
    const float4* a4 = (const float4*)anch;
    for (int p = tid; p < (Mn * 3) / 4; p += 256)
        ((float4*)o)[p] = a4[p];
}

// ---------------------------------------------------------------------------
// 3) Ball query + grouped conv. Joint 4-anchor chunk scan: each 32-point
//    chunk is loaded ONCE per warp and tested against all 4 anchors.
// ---------------------------------------------------------------------------
__global__ void __launch_bounds__(512)
group_conv_kernel(const float* __restrict__ xyz,
                  const float* __restrict__ anchors)
{
    extern __shared__ char smraw[];
    float4* npts = (float4*)smraw;                        // 32768 B
    float*  Ssm  = (float*)(smraw + 32768);               // 24576 B
    int*    cand = (int*)  (smraw + 32768 + 24576);       // 16 warps*128*4 = 8192 B

    int tile = blockIdx.x;
    int o    = blockIdx.y;
    int f    = blockIdx.z;
    int b = f >> 3, l = f & 7;
    int tid = threadIdx.x, lane = tid & 31, wid = tid >> 5;

    int ln = l + o - 1;
    if (ln < 0 || ln >= Ln) {
        for (int idx = tid; idx < 4096; idx += 512) {
            int kk = idx >> 6, mm = idx & 63;
            g_x[((size_t)f * KMn + o * MIDn + kk) * Mn + tile * 64 + mm] = 0.f;
        }
        return;
    }
    int nbr = b * Ln + ln;

    const float* nb = xyz + (size_t)nbr * Nn * 3;
    for (int p = tid; p < Nn; p += 512)
        npts[p] = make_float4(nb[3*p], nb[3*p+1], nb[3*p+2], 0.f);
    __syncthreads();

    int* candw = cand + wid * 128;   // 4 anchors x 32 slots
    const float* fb = g_ft + (size_t)nbr * Nn * Cn;

    // --- joint ball query for this warp's 4 anchors ---
    float ax[4], ay[4], az[4];
    int cnt[4] = {0, 0, 0, 0};
#pragma unroll
    for (int aa = 0; aa < 4; ++aa) {
        const float* ap = anchors + ((size_t)f * Mn + tile * 64 + wid * 4 + aa) * 3;
        ax[aa] = ap[0]; ay[aa] = ap[1]; az[aa] = ap[2];
    }
    for (int basej = 0; basej < Nn; basej += 32) {
        if (cnt[0] >= KSn && cnt[1] >= KSn && cnt[2] >= KSn && cnt[3] >= KSn)
            break;
        float4 p = npts[basej + lane];
#pragma unroll
        for (int aa = 0; aa < 4; ++aa) {
            if (cnt[aa] >= KSn) continue;           // warp-uniform branch
            float dx = p.x - ax[aa], dy = p.y - ay[aa], dz = p.z - az[aa];
            float d2 = fmaf(dx, dx, fmaf(dy, dy, dz * dz));
            bool in = d2 < 0.04f;
            unsigned msk = __ballot_sync(0xffffffffu, in);
            if (in) {
                int pos = cnt[aa] + __popc(msk & ((1u << lane) - 1u));
                if (pos < KSn) candw[aa * 32 + pos] = basej + lane;
            }
            cnt[aa] += __popc(msk);
        }
    }
    __syncwarp();
#pragma unroll
    for (int aa = 0; aa < 4; ++aa) {
        int cc = cnt[aa] < KSn ? cnt[aa] : KSn;
        int fill0 = (cc > 0) ? candw[aa * 32] : 0;
        __syncwarp();
        if (lane >= cc) candw[aa * 32 + lane] = fill0;
    }
    __syncwarp();

    // --- moment S[c,d] per anchor; lane = channel c ---
    for (int aa = 0; aa < 4; ++aa) {
        int a_local = wid * 4 + aa;
        float axx = ax[aa], ayy = ay[aa], azz = az[aa];
        float a0 = 0.f, a1 = 0.f, a2 = 0.f;
#pragma unroll 8
        for (int k = 0; k < KSn; ++k) {
            int j = candw[aa * 32 + k];
            float4 p = npts[j];
            float fv = __ldg(&fb[(size_t)j * Cn + lane]);
            a0 = fmaf(fv, p.x - axx, a0);
            a1 = fmaf(fv, p.y - ayy, a1);
            a2 = fmaf(fv, p.z - azz, a2);
        }
        Ssm[a_local * 96 + lane * 3 + 0] = a0;
        Ssm[a_local * 96 + lane * 3 + 1] = a1;
        Ssm[a_local * 96 + lane * 3 + 2] = a2;
    }
    __syncthreads();

    // --- GEMM: out[64 o][64 a] = W2[64][96] @ S^T (W2 via L1-hot __ldg) ---
    int o0 = (tid & 15) * 4;
    int aq = (tid >> 4) * 2;
    float acc[4][2] = {};
    for (int i = 0; i < 96; i += 4) {
        float4 w[4], s[2];
#pragma unroll
        for (int q = 0; q < 4; ++q) w[q] = __ldg((const float4*)&g_W2[(o0 + q) * 96 + i]);
#pragma unroll
        for (int r = 0; r < 2; ++r) s[r] = *(const float4*)&Ssm[(aq + r) * 96 + i];
#pragma unroll
        for (int q = 0; q < 4; ++q)
#pragma unroll
            for (int r = 0; r < 2; ++r)
                acc[q][r] += w[q].x * s[r].x + w[q].y * s[r].y
                           + w[q].z * s[r].z + w[q].w * s[r].w;
    }
#pragma unroll
    for (int q = 0; q < 4; ++q)
#pragma unroll
        for (int r = 0; r < 2; ++r)
            g_x[((size_t)f * KMn + o * MIDn + o0 + q) * Mn + tile * 64 + aq + r] = acc[q][r];
}

// ---------------------------------------------------------------------------
// 4) BN stats per (l, km) over 4096 values, float4 vectorized
// ---------------------------------------------------------------------------
__global__ void stats_kernel() {
    int pair = blockIdx.x;
    int l = pair / KMn, km = pair % KMn;
    int tid = threadIdx.x;
    float s1 = 0.f, s2 = 0.f;
#pragma unroll
    for (int b = 0; b < Bn; ++b) {
        const float4* row = (const float4*)(g_x + ((size_t)((b * Ln + l) * KMn + km)) * Mn);
#pragma unroll
        for (int m = 0; m < 2; ++m) {
            float4 v = row[tid + m * 128];
            s1 += v.x + v.y + v.z + v.w;
            s2 += v.x*v.x + v.y*v.y + v.z*v.z + v.w*v.w;
        }
    }
    __shared__ float sh1[4], sh2[4];
#pragma unroll
    for (int off = 16; off > 0; off >>= 1) {
        s1 += __shfl_down_sync(0xffffffffu, s1, off);
        s2 += __shfl_down_sync(0xffffffffu, s2, off);
    }
    int lane = tid & 31, w = tid >> 5;
    if (lane == 0) { sh1[w] = s1; sh2[w] = s2; }
    __syncthreads();
    if (tid == 0) {
        float t1 = sh1[0] + sh1[1] + sh1[2] + sh1[3];
        float t2 = sh2[0] + sh2[1] + sh2[2] + sh2[3];
        float mean = t1 * (1.f / 4096.f);
        float var  = t2 * (1.f / 4096.f) - mean * mean;
        g_mean[pair] = mean;
        g_rstd[pair] = rsqrtf(var + 1e-5f);
    }
}

// ---------------------------------------------------------------------------
// 5) Fused BN + ReLU + temporal GEMM
// ---------------------------------------------------------------------------
__global__ void __launch_bounds__(256)
bn_gemm_kernel(const float* __restrict__ gamma, const float* __restrict__ beta,
               const float* __restrict__ tw, float* __restrict__ dout)
{
    extern __shared__ float smf[];
    float* xsm  = smf;           // [192][128]
    float* twsm = smf + 24576;   // [128][192]

    int f = blockIdx.y, l = f & 7;
    int mb = blockIdx.x * 128;
    int tid = threadIdx.x;

    for (int idx = tid; idx < KMn * 128; idx += 256) {
        int k = idx >> 7, m = idx & 127;
        float v  = g_x[((size_t)f * KMn + k) * Mn + mb + m];
        float xn = (v - g_mean[l * KMn + k]) * g_rstd[l * KMn + k] * gamma[k] + beta[k];
        xsm[idx] = fmaxf(xn, 0.f);
    }
    for (int idx = tid; idx < OUTn * KMn; idx += 256) twsm[idx] = tw[idx];
    __syncthreads();

    int o0 = (tid >> 4) * 8;
    int m0 = (tid & 15) * 8;
    float acc[8][8] = {};
    for (int k = 0; k < KMn; k += 4) {
        float4 wv[8];
#pragma unroll
        for (int q = 0; q < 8; ++q) wv[q] = *(const float4*)&twsm[(o0 + q) * KMn + k];
        float4 xa[4], xb[4];
#pragma unroll
        for (int j = 0; j < 4; ++j) {
            xa[j] = *(const float4*)&xsm[(k + j) * 128 + m0];
            xb[j] = *(const float4*)&xsm[(k + j) * 128 + m0 + 4];
        }
#pragma unroll
        for (int q = 0; q < 8; ++q) {
            const float* wq = (const float*)&wv[q];
#pragma unroll
            for (int j = 0; j < 4; ++j) {
                float w = wq[j];
                const float* pa = (const float*)&xa[j];
                const float* pb = (const float*)&xb[j];
#pragma unroll
                for (int r = 0; r < 4; ++r) {
                    acc[q][r]     += w * pa[r];
                    acc[q][4 + r] += w * pb[r];
                }
            }
        }
    }
    float* outb = dout + (size_t)BLn * Mn * 3 + ((size_t)f * OUTn) * Mn + mb;
#pragma unroll
    for (int q = 0; q < 8; ++q)
#pragma unroll
        for (int r = 0; r < 8; ++r)
            outb[(size_t)(o0 + q) * Mn + m0 + r] = acc[q][r];
}

// ---------------------------------------------------------------------------
extern "C" void kernel_launch(void* const* d_in, const int* in_sizes, int n_in,
                              void* d_out, int out_size) {
    const float* xyzs     = (const float*)d_in[0];
    const float* features = (const float*)d_in[1];
    const float* cdw      = (const float*)d_in[2];
    const float* cfw      = (const float*)d_in[3];
    const float* gamma    = (const float*)d_in[4];
    const float* beta     = (const float*)d_in[5];
    const float* tw       = (const float*)d_in[6];
    float* out = (float*)d_out;

    cudaFuncSetAttribute(group_conv_kernel, cudaFuncAttributeMaxDynamicSharedMemorySize, 65536);
    cudaFuncSetAttribute(bn_gemm_kernel,    cudaFuncAttributeMaxDynamicSharedMemorySize, 196608);

    transpose_feat_kernel<<<dim3(64, 32), dim3(32, 32)>>>(features, cdw, cfw);
    nop_kernel<<<1, 32>>>();   // keep group_conv as the profiled (4th) launch
    fps_kernel<<<32, 256>>>(xyzs, out);
    group_conv_kernel<<<dim3(16, 3, 32), 512, 65536>>>(xyzs, out);
    stats_kernel<<<Ln * KMn, 128>>>();
    bn_gemm_kernel<<<dim3(8, 32), 256, 196608>>>(gamma, beta, tw, out);
}